// round 1
// baseline (speedup 1.0000x reference)
#include <cuda_runtime.h>

// CRF NLL: B=1024, T=4096, K=16
// inputs: d_in[0] = feats [B,T,K] f32, d_in[1] = tags [B,T] i32, d_in[2] = transitions [K,K] f32
// output: [B] f32 (forward_score - gold_score)

#define T_LEN 4096
#define KTAG 16
#define TILE 16
#define START_TAG 14
#define STOP_TAG 15

__global__ __launch_bounds__(128, 1)
void crf_nll_kernel(const float* __restrict__ feats,
                    const int* __restrict__ tags,
                    const float* __restrict__ trans,
                    float* __restrict__ out) {
    __shared__ float sExpT[256];   // exp(trans[j][i])
    __shared__ float sLogT[256];   // trans[j][i]

    int tid = threadIdx.x;
    for (int i = tid; i < 256; i += 128) {
        float tv = trans[i];
        sLogT[i] = tv;
        sExpT[i] = __expf(tv);     // exp(-10000) underflows to 0 -> correct masking
    }
    __syncthreads();

    int lane = tid & 31;
    int grp  = lane >> 4;          // 2 batch elements per warp
    int j    = lane & 15;          // this thread owns state p_j
    int warp = tid >> 5;
    int b = blockIdx.x * 8 + warp * 2 + grp;

    // row M[j][:] in registers
    float Mr[16];
    #pragma unroll
    for (int i = 0; i < 16; i++) Mr[i] = sExpT[j * 16 + i];
    float Mstop = sExpT[STOP_TAG * 16 + j];

    const float* fptr = feats + ((long long)b * T_LEN) * KTAG + j;
    const int*   tptr = tags  + (long long)b * T_LEN;

    // p = exp(alpha0): 1 at START, 0 elsewhere
    float p = (j == START_TAG) ? 1.0f : 0.0f;
    int   esum = 0;        // exact power-of-2 log-scale accumulator
    float gold = 0.0f;
    int   prevtag = START_TAG;

    float fA[TILE], fB[TILE];
    int   gA[TILE], gB[TILE];

    // prime first tile
    #pragma unroll
    for (int u = 0; u < TILE; u++) fA[u] = fptr[u * KTAG];
    {
        const int4* tp4 = reinterpret_cast<const int4*>(tptr);
        #pragma unroll
        for (int q = 0; q < TILE / 4; q++) {
            int4 v = tp4[q];
            gA[4*q+0] = v.x; gA[4*q+1] = v.y; gA[4*q+2] = v.z; gA[4*q+3] = v.w;
        }
    }

    const int NT = T_LEN / TILE;   // 256 tiles
    #pragma unroll 1
    for (int tile = 0; tile < NT; tile++) {
        // prefetch next tile (one full tile ahead ~ 1000 cycles)
        if (tile + 1 < NT) {
            int base = (tile + 1) * TILE;
            #pragma unroll
            for (int u = 0; u < TILE; u++) fB[u] = fptr[(base + u) * KTAG];
            const int4* tp4 = reinterpret_cast<const int4*>(tptr + base);
            #pragma unroll
            for (int q = 0; q < TILE / 4; q++) {
                int4 v = tp4[q];
                gB[4*q+0] = v.x; gB[4*q+1] = v.y; gB[4*q+2] = v.z; gB[4*q+3] = v.w;
            }
        }

        #pragma unroll
        for (int u = 0; u < TILE; u++) {
            float f  = fA[u];
            int   tg = gA[u];
            float ef = __expf(f);

            // s_j = sum_i M[j,i] * p_i   (p broadcast via width-16 shuffles)
            float a0 = 0.f, a1 = 0.f, a2 = 0.f, a3 = 0.f;
            #pragma unroll
            for (int i = 0; i < 16; i += 4) {
                a0 = fmaf(Mr[i+0], __shfl_sync(0xffffffffu, p, i+0, 16), a0);
                a1 = fmaf(Mr[i+1], __shfl_sync(0xffffffffu, p, i+1, 16), a1);
                a2 = fmaf(Mr[i+2], __shfl_sync(0xffffffffu, p, i+2, 16), a2);
                a3 = fmaf(Mr[i+3], __shfl_sync(0xffffffffu, p, i+3, 16), a3);
            }
            float s = (a0 + a1) + (a2 + a3);
            p = s * ef;

            // gold score: emit + transition
            float emit = __shfl_sync(0xffffffffu, f, tg, 16);
            gold += emit + sLogT[tg * 16 + prevtag];
            prevtag = tg;

            // exact pow2 renormalization every 4 steps
            if ((u & 3) == 3) {
                float m = p;
                m = fmaxf(m, __shfl_xor_sync(0xffffffffu, m, 1, 16));
                m = fmaxf(m, __shfl_xor_sync(0xffffffffu, m, 2, 16));
                m = fmaxf(m, __shfl_xor_sync(0xffffffffu, m, 4, 16));
                m = fmaxf(m, __shfl_xor_sync(0xffffffffu, m, 8, 16));
                int e = (__float_as_int(m) >> 23) & 255;
                p *= __int_as_float((254 - e) << 23);   // * 2^(127-e), exact
                esum += e - 127;
            }
        }

        // rotate buffers
        #pragma unroll
        for (int u = 0; u < TILE; u++) { fA[u] = fB[u]; gA[u] = gB[u]; }
    }

    // forward_score = esum*ln2 + log( sum_j exp(trans[STOP,j]) * p_j )
    float v = Mstop * p;
    v += __shfl_xor_sync(0xffffffffu, v, 1, 16);
    v += __shfl_xor_sync(0xffffffffu, v, 2, 16);
    v += __shfl_xor_sync(0xffffffffu, v, 4, 16);
    v += __shfl_xor_sync(0xffffffffu, v, 8, 16);

    double fwd = (double)esum * 0.6931471805599453 + (double)__logf(v);
    float goldT = gold + sLogT[STOP_TAG * 16 + prevtag];

    if (j == 0) out[b] = (float)(fwd - (double)goldT);
}

extern "C" void kernel_launch(void* const* d_in, const int* in_sizes, int n_in,
                              void* d_out, int out_size) {
    const float* feats = (const float*)d_in[0];
    const int*   tags  = (const int*)d_in[1];
    const float* trans = (const float*)d_in[2];
    float* out = (float*)d_out;

    int B = in_sizes[1] / T_LEN;           // 1024
    int blocks = B / 8;                    // 8 batch elements per 128-thread block
    crf_nll_kernel<<<blocks, 128>>>(feats, tags, trans, out);
}

// round 2
// speedup vs baseline: 1.4202x; 1.4202x over previous
#include <cuda_runtime.h>

// CRF NLL: B=1024, T=4096, K=16
// d_in[0]=feats [B,T,K] f32, d_in[1]=tags [B,T] i32, d_in[2]=transitions [K,K] f32
// out: [B] f32

#define T_LEN 4096
#define KTAG 16
#define TILE 16
#define START_TAG 14
#define STOP_TAG 15

__global__ __launch_bounds__(128, 1)
void crf_nll_kernel(const float* __restrict__ feats,
                    const int* __restrict__ tags,
                    const float* __restrict__ trans,
                    float* __restrict__ out) {
    __shared__ float sExpT[256];   // exp(trans[j][i])
    __shared__ float sLogT[256];   // trans[j][i]
    __shared__ float sP[8][16];    // per-element probability vector

    int tid = threadIdx.x;
    for (int i = tid; i < 256; i += 128) {
        float tv = trans[i];
        sLogT[i] = tv;
        sExpT[i] = __expf(tv);     // exp(-10000) -> 0, correct masking
    }

    int lane = tid & 31;
    int grp  = lane >> 4;          // 2 batch elements per warp
    int j    = lane & 15;          // this thread owns state j
    int warp = tid >> 5;
    int g    = warp * 2 + grp;     // element slot within block (0..7)
    int b    = blockIdx.x * 8 + g;

    __syncthreads();

    // row M[j][:] in registers
    float Mr[16];
    #pragma unroll
    for (int i = 0; i < 16; i++) Mr[i] = sExpT[j * 16 + i];
    float Mstop = sExpT[STOP_TAG * 16 + j];

    const float* fbase = feats + (size_t)b * T_LEN * KTAG;
    const int*   tptr  = tags  + (size_t)b * T_LEN;

    // p = exp(alpha0): 1 at START, 0 elsewhere
    sP[g][j] = (j == START_TAG) ? 1.0f : 0.0f;
    __syncthreads();

    int   esum = 0;        // exact power-of-2 scale accumulator
    float gold = 0.0f;
    int   prevtag = START_TAG;
    float pnew = 0.0f;

    float fA[TILE], fB[TILE];
    int   gA[TILE], gB[TILE];

    // prime first tile
    #pragma unroll
    for (int u = 0; u < TILE; u++) fA[u] = fbase[u * KTAG + j];
    {
        const int4* tp4 = reinterpret_cast<const int4*>(tptr);
        #pragma unroll
        for (int q = 0; q < TILE / 4; q++) {
            int4 v = tp4[q];
            gA[4*q+0] = v.x; gA[4*q+1] = v.y; gA[4*q+2] = v.z; gA[4*q+3] = v.w;
        }
    }

    const int NT = T_LEN / TILE;   // 256 tiles
    #pragma unroll 1
    for (int tile = 0; tile < NT; tile++) {
        // prefetch next tile (~1400 cycles ahead of use)
        if (tile + 1 < NT) {
            int base = (tile + 1) * TILE;
            #pragma unroll
            for (int u = 0; u < TILE; u++) fB[u] = fbase[(base + u) * KTAG + j];
            const int4* tp4 = reinterpret_cast<const int4*>(tptr + base);
            #pragma unroll
            for (int q = 0; q < TILE / 4; q++) {
                int4 v = tp4[q];
                gB[4*q+0] = v.x; gB[4*q+1] = v.y; gB[4*q+2] = v.z; gB[4*q+3] = v.w;
            }
        }
        int tbase = tile * TILE;

        #pragma unroll
        for (int u = 0; u < TILE; u++) {
            float f  = fA[u];
            int   tg = gA[u];
            float ef = __expf(f);

            // broadcast p via smem: conflict-free broadcast reads
            __syncwarp();
            float4 q0 = *reinterpret_cast<const float4*>(&sP[g][0]);
            float4 q1 = *reinterpret_cast<const float4*>(&sP[g][4]);
            float4 q2 = *reinterpret_cast<const float4*>(&sP[g][8]);
            float4 q3 = *reinterpret_cast<const float4*>(&sP[g][12]);

            // exact pow2 renorm every 4 steps: scale computed redundantly per
            // lane from the full vector (ALU only, off the FMA chain)
            if ((u & 3) == 3) {
                float m0 = fmaxf(fmaxf(q0.x, q0.y), fmaxf(q0.z, q0.w));
                float m1 = fmaxf(fmaxf(q1.x, q1.y), fmaxf(q1.z, q1.w));
                float m2 = fmaxf(fmaxf(q2.x, q2.y), fmaxf(q2.z, q2.w));
                float m3 = fmaxf(fmaxf(q3.x, q3.y), fmaxf(q3.z, q3.w));
                float m  = fmaxf(fmaxf(m0, m1), fmaxf(m2, m3));
                int e = (__float_as_int(m) >> 23) & 255;
                ef *= __int_as_float((254 - e) << 23);   // * 2^(127-e), exact
                esum += e - 127;
            }

            // s_j = sum_i M[j,i] * p_i; each accumulator's tail FMA depends
            // only on the last-arriving quad
            float a0 = fmaf(q3.x, Mr[12], fmaf(q2.x, Mr[ 8], fmaf(q1.x, Mr[4], q0.x * Mr[0])));
            float a1 = fmaf(q3.y, Mr[13], fmaf(q2.y, Mr[ 9], fmaf(q1.y, Mr[5], q0.y * Mr[1])));
            float a2 = fmaf(q3.z, Mr[14], fmaf(q2.z, Mr[10], fmaf(q1.z, Mr[6], q0.z * Mr[2])));
            float a3 = fmaf(q3.w, Mr[15], fmaf(q2.w, Mr[11], fmaf(q1.w, Mr[7], q0.w * Mr[3])));
            float s = (a0 + a1) + (a2 + a3);
            pnew = s * ef;
            sP[g][j] = pnew;

            // gold score: uniform L1-hot gather + smem transition lookup
            gold += fbase[(tbase + u) * KTAG + tg] + sLogT[tg * 16 + prevtag];
            prevtag = tg;
        }

        #pragma unroll
        for (int u = 0; u < TILE; u++) { fA[u] = fB[u]; gA[u] = gB[u]; }
    }

    // forward_score = esum*ln2 + log( sum_j exp(trans[STOP,j]) * p_j )
    float v = Mstop * pnew;
    v += __shfl_xor_sync(0xffffffffu, v, 1, 16);
    v += __shfl_xor_sync(0xffffffffu, v, 2, 16);
    v += __shfl_xor_sync(0xffffffffu, v, 4, 16);
    v += __shfl_xor_sync(0xffffffffu, v, 8, 16);

    double fwd = (double)esum * 0.6931471805599453 + (double)__logf(v);
    float goldT = gold + sLogT[STOP_TAG * 16 + prevtag];

    if (j == 0) out[b] = (float)(fwd - (double)goldT);
}

extern "C" void kernel_launch(void* const* d_in, const int* in_sizes, int n_in,
                              void* d_out, int out_size) {
    const float* feats = (const float*)d_in[0];
    const int*   tags  = (const int*)d_in[1];
    const float* trans = (const float*)d_in[2];
    float* out = (float*)d_out;

    int B = in_sizes[1] / T_LEN;           // 1024
    int blocks = B / 8;                    // 8 batch elements per 128-thread block
    crf_nll_kernel<<<blocks, 128>>>(feats, tags, trans, out);
}